// round 4
// baseline (speedup 1.0000x reference)
#include <cuda_runtime.h>

#define NB   10
#define TW   120      // output columns per block
#define CH   64       // output rows per block chunk
#define HH   512
#define WW   512
#define OH   507
#define OW   507
#define NTH  128
#define XW   129      // x columns staged per block (TW + 9)

__device__ __forceinline__ float pmod10(float v) {
    float r = fmodf(v, 10.0f);
    return (r < 0.0f) ? r + 10.0f : r;
}

__device__ __forceinline__ int slot3(int row) {
    return ((row % 3) + 3) % 3;
}

__global__ __launch_bounds__(NTH)
void hog_fused_kernel(const float* __restrict__ x,
                      const float* __restrict__ wgt,
                      float* __restrict__ out,
                      int nbatch) {
    __shared__ float xs[3][XW + 3];        // 3-row ring of input rows
    __shared__ float hrow[NB][NTH];        // dense per-row histogram, cols j=0..126
    __shared__ float ring[NB][8][TW];      // last 8 horizontal sums per bin/col

    const int tid = threadIdx.x;
    const int n   = blockIdx.z;
    const int ox0 = blockIdx.x * TW;
    const int oy0 = blockIdx.y * CH;
    const int nrows = min(CH, OH - oy0);
    if (n >= nbatch) return;

    // Load the 2x(3x3) sobel weights into registers (L2-cached, negligible)
    float w0[9], w1[9];
#pragma unroll
    for (int i = 0; i < 9; i++) { w0[i] = wgt[i]; w1[i] = wgt[9 + i]; }

    const int ox = ox0 + tid;
    const bool out_ok = (tid < TW) && (ox < OW);

    // zero the vertical ring buffer
    for (int i = tid; i < NB * 8 * TW; i += NTH)
        ((float*)ring)[i] = 0.0f;

    // ---- x row staging helper (zero-pads out-of-range rows/cols) ----
    const float* xbase = x + (size_t)n * HH * WW;
#define LOAD_XROW(ROW)                                                        \
    do {                                                                      \
        int _row = (ROW);                                                     \
        int _sl = slot3(_row);                                                \
        const float* _src = xbase + (size_t)_row * WW;                        \
        for (int lx = tid; lx < XW; lx += NTH) {                              \
            int gc = ox0 - 2 + lx;                                            \
            float v = 0.0f;                                                   \
            if (_row >= 0 && _row < HH && gc >= 0 && gc < WW) v = _src[gc];   \
            xs[_sl][lx] = v;                                                  \
        }                                                                     \
    } while (0)

    // preload rows oy0-2 and oy0-1
    LOAD_XROW(oy0 - 2);
    LOAD_XROW(oy0 - 1);

    float acc[NB];
#pragma unroll
    for (int b = 0; b < NB; b++) acc[b] = 0.0f;

    const int iters = nrows + 7;  // hist rows oy0-1 .. oy0+nrows+5
    for (int it = 0; it < iters; it++) {
        const int hy = oy0 - 1 + it;

        __syncthreads();  // prev hsum reads + prev hist x reads done

        // zero hrow (bank-conflict-free: bank = tid%32)
#pragma unroll
        for (int b = 0; b < NB; b++) hrow[b][tid] = 0.0f;

        // stage next x row (hy+1)
        LOAD_XROW(hy + 1);

        __syncthreads();  // hrow zeroed + x row visible

        // ---- per-pixel histogram contribution, scatter into hrow ----
        if (tid < TW + 7 && hy >= 0 && hy < HH) {
            const int hc = ox0 - 1 + tid;
            if (hc >= 0 && hc < WW) {
                const int s0 = slot3(hy - 1);
                const int s1 = slot3(hy);
                const int s2 = slot3(hy + 1);
                float a0 = xs[s0][tid], a1 = xs[s0][tid + 1], a2 = xs[s0][tid + 2];
                float b0 = xs[s1][tid], b1 = xs[s1][tid + 1], b2 = xs[s1][tid + 2];
                float c0 = xs[s2][tid], c1 = xs[s2][tid + 1], c2 = xs[s2][tid + 2];

                float g0 = w0[0]*a0 + w0[1]*a1 + w0[2]*a2
                         + w0[3]*b0 + w0[4]*b1 + w0[5]*b2
                         + w0[6]*c0 + w0[7]*c1 + w0[8]*c2;
                float g1 = w1[0]*a0 + w1[1]*a1 + w1[2]*a2
                         + w1[3]*b0 + w1[4]*b1 + w1[5]*b2
                         + w1[6]*c0 + w1[7]*c1 + w1[8]*c2;

                float nrm = sqrtf(g0 * g0 + g1 * g1);
                float ph  = atan2f(g0, g1);
                float pint = ph / 3.14159274f * 10.0f;   // phase / pi * NBINS

                float fl = floorf(pint);
                float cl = ceilf(pint);
                float f  = pmod10(pint);
                float bm = pmod10(fl);
                float tm = pmod10(cl);
                float t_v = nrm * (1.0f - (tm - f));
                float b_v = nrm * (1.0f - (f - bm));

                int ib = (int)fl % 10; if (ib < 0) ib += 10;
                int ic = (int)cl % 10; if (ic < 0) ic += 10;

                // exclusive column per thread -> plain stores, no atomics
                hrow[ib][tid] = b_v;
                hrow[ic][tid] = (ic == ib) ? (b_v + t_v) : t_v;
            }
        }

        __syncthreads();  // hrow scatter visible

        // ---- horizontal 8-sum + vertical running sum + store ----
        if (out_ok) {
            const int r = it & 7;
#pragma unroll
            for (int b = 0; b < NB; b++) {
                float s = 0.0f;
#pragma unroll
                for (int d = 0; d < 8; d++) s += hrow[b][tid + d];
                acc[b] += s - ring[b][r][tid];
                ring[b][r][tid] = s;
            }
            if (it >= 7) {
                const int oy = hy - 6;
#pragma unroll
                for (int b = 0; b < NB; b++)
                    out[(((size_t)n * NB + b) * OH + oy) * OW + ox] =
                        acc[b] * (1.0f / 64.0f);
            }
        }
    }
#undef LOAD_XROW
}

extern "C" void kernel_launch(void* const* d_in, const int* in_sizes, int n_in,
                              void* d_out, int out_size) {
    const float* x = (const float*)d_in[0];
    const float* w = (const float*)d_in[1];
    float* out = (float*)d_out;

    const int nbatch = in_sizes[0] / (HH * WW);  // 32

    dim3 grid((OW + TW - 1) / TW,   // 5
              (OH + CH - 1) / CH,   // 8
              nbatch);              // 32
    hog_fused_kernel<<<grid, NTH>>>(x, w, out, nbatch);
}